// round 8
// baseline (speedup 1.0000x reference)
#include <cuda_runtime.h>
#include <cuda_fp16.h>
#include <cstdint>

#define B_   8
#define T_   2048
#define N_   512
#define M_   (B_*T_)      // 16384
#define L_   64           // scan chunk length
#define NCH_ (T_/L_)      // 32

#define WSCALE 64.0f
#define WINV   (1.0f/64.0f)

typedef unsigned long long ull;

// Scratch
__device__ __half2 g_xh[M_*N_];               // x as fp16 complex (re=low, im=high)
__device__ float2  g_end[B_*NCH_*N_];
// Pre-transposed/swizzled fp16 weight tiles (scaled by WSCALE):
__device__ uint4 g_W1[8][8][1024];            // GEMM1 B'' (Neff=1024, K=512), 128-row blocks
__device__ uint4 g_W2[4][16][1024];           // GEMM2 B'  (N=512, Keff=1024), 128-row blocks

// ---------------------------------------------------------------------------
// Helpers
// ---------------------------------------------------------------------------
__device__ __forceinline__ uint32_t s2u(const void* p){
    uint32_t a;
    asm("{ .reg .u64 t; cvta.to.shared.u64 t, %1; cvt.u32.u64 %0, t; }" : "=r"(a) : "l"(p));
    return a;
}
#define SWZ(o) ((uint32_t)(o) ^ ((((uint32_t)(o))>>3)&0x70u))

__device__ __forceinline__ uint32_t cvt2h(float x0, float x1){
    uint32_t r;
    asm("cvt.rn.f16x2.f32 %0, %1, %2;" : "=r"(r) : "f"(x1), "f"(x0));
    return r;
}
__device__ __forceinline__ uint4 ldsm4(uint32_t addr){
    uint4 r;
    asm volatile("ldmatrix.sync.aligned.m8n8.x4.shared.b16 {%0,%1,%2,%3}, [%4];"
        : "=r"(r.x), "=r"(r.y), "=r"(r.z), "=r"(r.w) : "r"(addr));
    return r;
}
__device__ __forceinline__ void mma16816(float* c, uint4 a, uint32_t b0, uint32_t b1){
    asm volatile("mma.sync.aligned.m16n8k16.row.col.f32.f16.f16.f32 "
        "{%0,%1,%2,%3}, {%4,%5,%6,%7}, {%8,%9}, {%0,%1,%2,%3};"
        : "+f"(c[0]), "+f"(c[1]), "+f"(c[2]), "+f"(c[3])
        : "r"(a.x), "r"(a.y), "r"(a.z), "r"(a.w), "r"(b0), "r"(b1));
}
__device__ __forceinline__ void cpasync16(uint32_t dst, const void* src){
    asm volatile("cp.async.cg.shared.global [%0], [%1], 16;" :: "r"(dst), "l"(src));
}

// ---------------------------------------------------------------------------
// Prepass (smem-transposed, coalesced loads).
//  bid <  128: W1 tiles. block = (kb in 0..7, nt in 0..15): k-range 64, n-range 32 (-> 64 j rows)
//  bid >= 128: W2 tiles. block = (kb in 0..15, jt in 0..7): k-range 32 (64 keff), j-range 64
// ---------------------------------------------------------------------------
__global__ __launch_bounds__(256) void prep_W(const float* __restrict__ Bre,
                                              const float* __restrict__ Bim,
                                              const float* __restrict__ Cre,
                                              const float* __restrict__ Cim,
                                              const float* __restrict__ gamma)
{
    __shared__ float s0[64*36];
    __shared__ float s1[64*36];
    __shared__ float gs[64];
    int bid = blockIdx.x, tid = threadIdx.x;

    if (bid < 128){
        int kb = bid >> 4, nt = bid & 15;
        int n0 = nt*32, k0 = kb*64;
        #pragma unroll
        for (int i = 0; i < 2; i++){
            int idx = tid + 256*i;
            int row = idx >> 3, c4 = (idx & 7) * 4;
            *(float4*)&s0[row*36 + c4] = *(const float4*)&Bre[(size_t)(k0+row)*N_ + n0 + c4];
            *(float4*)&s1[row*36 + c4] = *(const float4*)&Bim[(size_t)(k0+row)*N_ + n0 + c4];
        }
        if (tid < 64) gs[tid] = gamma[k0 + tid];
        __syncthreads();
        #pragma unroll
        for (int i = 0; i < 2; i++){
            int uid = tid + 256*i;
            int jloc = uid >> 3, cl = uid & 7;
            int j = n0*2 + jloc;
            int nloc = jloc >> 1, p = jloc & 1;
            const float* sp = p ? s1 : s0;
            float vs[8];
            #pragma unroll
            for (int e = 0; e < 8; e++){
                int kl = cl*8 + e;
                vs[e] = sp[kl*36 + nloc] * gs[kl] * WSCALE;
            }
            uint4 H;
            H.x = cvt2h(vs[0], vs[1]);
            H.y = cvt2h(vs[2], vs[3]);
            H.z = cvt2h(vs[4], vs[5]);
            H.w = cvt2h(vs[6], vs[7]);
            int jl = j & 127;
            g_W1[j>>7][kb][jl*8 + (cl ^ (jl & 7))] = H;
        }
    } else {
        bid -= 128;
        int kb = bid >> 3, jt = bid & 7;
        int j0 = jt*64, k0 = kb*32;
        #pragma unroll
        for (int i = 0; i < 2; i++){
            int idx = tid + 256*i;
            int row = idx >> 4, c4 = (idx & 15) * 4;
            *(float4*)&s0[row*68 + c4] = *(const float4*)&Cre[(size_t)(k0+row)*N_ + j0 + c4];
            *(float4*)&s1[row*68 + c4] = *(const float4*)&Cim[(size_t)(k0+row)*N_ + j0 + c4];
        }
        __syncthreads();
        #pragma unroll
        for (int i = 0; i < 2; i++){
            int uid = tid + 256*i;
            int jloc = uid >> 3, cl = uid & 7;
            int j = j0 + jloc;
            float vs[8];
            #pragma unroll
            for (int e = 0; e < 8; e++){
                int kel = cl*8 + e;
                int kl = kel >> 1;
                float v = (kel & 1) ? -s1[kl*68 + jloc] : s0[kl*68 + jloc];
                vs[e] = v * WSCALE;
            }
            uint4 H;
            H.x = cvt2h(vs[0], vs[1]);
            H.y = cvt2h(vs[2], vs[3]);
            H.z = cvt2h(vs[4], vs[5]);
            H.w = cvt2h(vs[6], vs[7]);
            int jl = j & 127;
            g_W2[j>>7][kb][jl*8 + (cl ^ (jl & 7))] = H;
        }
    }
}

// ---------------------------------------------------------------------------
// HMMA GEMM, single fp16 product, double-buffered, wave-balanced tiles.
// MODE 1: g_xh = u @ W1,            tile 128x64,  grid (16 nb, 128 mb) = 2048 CTAs
// MODE 2: y = flat16(g_xh) @ W2+D*u, tile 128x32, grid (16 nb, 128 mb) = 2048 CTAs
// 8 warps. MODE1 warps 4x2 (warp 32x32); MODE2 warps 8x1 (warp 16x32).
// ---------------------------------------------------------------------------
template<int MODE>
__global__ __launch_bounds__(256, 2) void gemm_tc(const float* __restrict__ Aglob,
                                                  const float* __restrict__ Dv,
                                                  const float* __restrict__ uu,
                                                  float* __restrict__ yout)
{
    constexpr int KIT    = (MODE == 1) ? 8 : 16;
    constexpr int NTILE  = (MODE == 1) ? 64 : 32;
    constexpr int WM     = (MODE == 1) ? 4 : 8;       // warps in m
    constexpr int WROWS  = 128 / WM;                  // rows per warp (32 / 16)
    constexpr int MT_I   = WROWS / 16;                // m16 frags (2 / 1)
    constexpr int NT_I   = 4;                         // n8 frags per warp (32 n)
    constexpr int BUNITS = NTILE * 8;                 // 16B units per B tile (512/256)
    constexpr uint32_t BBYTES = NTILE * 128;
    constexpr uint32_t STG = 16384 + BBYTES;
    constexpr uint32_t AH = 0, BH = 16384;

    extern __shared__ char sm[];
    const uint32_t sb = s2u(sm);

    const int tid  = threadIdx.x;
    const int lane = tid & 31, warp = tid >> 5;
    const int wm = (MODE == 1) ? (warp >> 1) : warp;
    const int wn = (MODE == 1) ? (warp & 1) : 0;
    const int nb = blockIdx.x;              // n-block FAST -> A stripe reuse in L2
    const int m0 = blockIdx.y * 128;

    const uint4* Wb = (MODE == 1)
        ? (&g_W1[nb>>1][0][0] + (nb&1)*512)
        : (&g_W2[nb>>2][0][0] + (nb&3)*256);

    float acc[MT_I][NT_I][4];
    #pragma unroll
    for (int a = 0; a < MT_I; a++)
        #pragma unroll
        for (int b = 0; b < NT_I; b++)
            #pragma unroll
            for (int q = 0; q < 4; q++) acc[a][b][q] = 0.f;

    // MODE1 A-load mapping (fp32 -> cvt)
    const int arow = tid >> 1;
    const int akg  = (tid & 1) * 32;
    const float* aptr = (MODE == 1) ? (Aglob + (size_t)(m0 + arow) * 512 + akg) : (const float*)0;
    float4 f[8];

    // ---- prologue: stage 0 ----
    {
        #pragma unroll
        for (int i = 0; i < BUNITS/256; i++)
            cpasync16(sb + BH + (tid + 256*i)*16, Wb + tid + 256*i);
        if (MODE == 2){
            #pragma unroll
            for (int i = 0; i < 4; i++){
                int idx = tid + 256*i, row = idx >> 3, un = idx & 7;
                cpasync16(sb + AH + SWZ(row*128 + un*16),
                          (const uint4*)(g_xh + (size_t)(m0+row)*512) + un);
            }
        }
        asm volatile("cp.async.commit_group;");
        if (MODE == 1){
            const float4* ap = (const float4*)aptr;
            #pragma unroll
            for (int j = 0; j < 8; j++) f[j] = ap[j];
            #pragma unroll
            for (int j = 0; j < 4; j++){
                uint4 H;
                H.x = cvt2h(f[2*j].x,   f[2*j].y);
                H.y = cvt2h(f[2*j].z,   f[2*j].w);
                H.z = cvt2h(f[2*j+1].x, f[2*j+1].y);
                H.w = cvt2h(f[2*j+1].z, f[2*j+1].w);
                *(uint4*)(sm + AH + SWZ(arow*128 + (tid&1)*64 + j*16)) = H;
            }
        }
    }

    for (int kb = 0; kb < KIT; kb++){
        const int cur = kb & 1, nxt = cur ^ 1;
        const uint32_t sc = sb + cur*STG;
        char* smn = sm + nxt*STG;
        const uint32_t sn = sb + nxt*STG;

        if (kb + 1 < KIT){
            const uint4* wh = Wb + (kb+1)*1024;
            #pragma unroll
            for (int i = 0; i < BUNITS/256; i++)
                cpasync16(sn + BH + (tid + 256*i)*16, wh + tid + 256*i);
            if (MODE == 2){
                #pragma unroll
                for (int i = 0; i < 4; i++){
                    int idx = tid + 256*i, row = idx >> 3, un = idx & 7;
                    cpasync16(sn + AH + SWZ(row*128 + un*16),
                              (const uint4*)(g_xh + (size_t)(m0+row)*512 + (kb+1)*32) + un);
                }
            }
            asm volatile("cp.async.commit_group;");
            if (MODE == 1){
                const float4* ap = (const float4*)(aptr + (kb+1)*64);
                #pragma unroll
                for (int j = 0; j < 8; j++) f[j] = ap[j];
            }
            asm volatile("cp.async.wait_group 1;" ::: "memory");
        } else {
            asm volatile("cp.async.wait_group 0;" ::: "memory");
        }
        __syncthreads();

        #pragma unroll
        for (int kk = 0; kk < 4; kk++){
            uint4 ah[MT_I];
            #pragma unroll
            for (int mt = 0; mt < MT_I; mt++){
                uint32_t off = SWZ((wm*WROWS + mt*16 + (lane&15))*128 + (kk*2 + (lane>>4))*16);
                ah[mt] = ldsm4(sc + AH + off);
            }
            #pragma unroll
            for (int bt = 0; bt < NT_I/2; bt++){
                uint32_t off = SWZ((wn*32 + bt*16 + (lane&7) + ((lane>>4)<<3))*128
                                   + (kk*2 + ((lane>>3)&1))*16);
                uint4 bh = ldsm4(sc + BH + off);
                #pragma unroll
                for (int mt = 0; mt < MT_I; mt++){
                    mma16816(acc[mt][2*bt],   ah[mt], bh.x, bh.y);
                    mma16816(acc[mt][2*bt+1], ah[mt], bh.z, bh.w);
                }
            }
        }

        if (MODE == 1 && kb + 1 < KIT){
            #pragma unroll
            for (int j = 0; j < 4; j++){
                uint4 H;
                H.x = cvt2h(f[2*j].x,   f[2*j].y);
                H.y = cvt2h(f[2*j].z,   f[2*j].w);
                H.z = cvt2h(f[2*j+1].x, f[2*j+1].y);
                H.w = cvt2h(f[2*j+1].z, f[2*j+1].w);
                *(uint4*)(smn + AH + SWZ(arow*128 + (tid&1)*64 + j*16)) = H;
            }
        }
        __syncthreads();
    }

    // Epilogue (undo WSCALE)
    const int mrow = lane >> 2;
    const int ncol = (lane & 3) * 2;
    if (MODE == 1){
        #pragma unroll
        for (int mt = 0; mt < MT_I; mt++){
            #pragma unroll
            for (int nf = 0; nf < NT_I; nf++){
                int m    = m0 + wm*WROWS + mt*16 + mrow;
                int neff = nb*NTILE + wn*32 + nf*8 + ncol;
                int nc   = neff >> 1;
                g_xh[(size_t)m*N_ + nc]     = __floats2half2_rn(acc[mt][nf][0]*WINV, acc[mt][nf][1]*WINV);
                g_xh[(size_t)(m+8)*N_ + nc] = __floats2half2_rn(acc[mt][nf][2]*WINV, acc[mt][nf][3]*WINV);
            }
        }
    } else {
        #pragma unroll
        for (int mt = 0; mt < MT_I; mt++){
            #pragma unroll
            for (int nf = 0; nf < NT_I; nf++){
                int m = m0 + wm*WROWS + mt*16 + mrow;
                int n = nb*NTILE + nf*8 + ncol;
                float2 d = *(const float2*)&Dv[n];
                size_t i0 = (size_t)m*N_ + n;
                size_t i1 = (size_t)(m+8)*N_ + n;
                float2 u0 = *(const float2*)&uu[i0];
                float2 u1 = *(const float2*)&uu[i1];
                float2 y0 = make_float2(fmaf(d.x, u0.x, acc[mt][nf][0]*WINV),
                                        fmaf(d.y, u0.y, acc[mt][nf][1]*WINV));
                float2 y1 = make_float2(fmaf(d.x, u1.x, acc[mt][nf][2]*WINV),
                                        fmaf(d.y, u1.y, acc[mt][nf][3]*WINV));
                *(float2*)&yout[i0] = y0;
                *(float2*)&yout[i1] = y1;
            }
        }
    }
}

// ---------------------------------------------------------------------------
// Scan pass 1: chunk end-states only (read-only): e = sum_t lam^{L-1-t} u_t
// ---------------------------------------------------------------------------
__global__ __launch_bounds__(256) void scan_ends(const float* __restrict__ nu,
                                                 const float* __restrict__ theta)
{
    int gid = blockIdx.x * 256 + threadIdx.x;   // 131072 threads
    int n = gid & (N_-1);
    int c = (gid >> 9) & (NCH_-1);
    int b = gid >> 14;

    float en  = expf(nu[n]);
    float mag = expf(-en);
    float th  = theta[n];
    float lr  = mag * cosf(th);
    float li  = mag * sinf(th);

    const __half2* p = g_xh + ((size_t)(b*T_ + c*L_))*N_ + n;
    float er = 0.f, ei = 0.f;
    for (int t0 = 0; t0 < L_; t0 += 16){
        __half2 v[16];
        #pragma unroll
        for (int j = 0; j < 16; j++) v[j] = p[(size_t)(t0+j)*N_];
        #pragma unroll
        for (int j = 0; j < 16; j++){
            float2 q = __half22float2(v[j]);
            float nr = fmaf(lr, er, fmaf(-li, ei, q.x));
            float ni = fmaf(lr, ei, fmaf( li, er, q.y));
            er = nr; ei = ni;
        }
    }
    g_end[(b*NCH_ + c)*N_ + n] = make_float2(er, ei);
}

// ---------------------------------------------------------------------------
// Scan pass 2: carry from previous chunk-ends, then full recurrence, write x.
// ---------------------------------------------------------------------------
__global__ __launch_bounds__(256) void scan_apply(const float* __restrict__ nu,
                                                  const float* __restrict__ theta)
{
    int gid = blockIdx.x * 256 + threadIdx.x;
    int n = gid & (N_-1);
    int c = (gid >> 9) & (NCH_-1);
    int b = gid >> 14;

    float en  = expf(nu[n]);
    float mag = expf(-en);
    float th  = theta[n];
    float lr  = mag * cosf(th);
    float li  = mag * sinf(th);

    float magL = expf(-(float)L_ * en);
    float aL   = (float)L_ * th;
    float lLr  = magL * cosf(aL);
    float lLi  = magL * sinf(aL);

    // carry = sum_{j<c} end[j] * lamL^{c-1-j} (Horner)
    float cr = 0.f, ci = 0.f;
    for (int j = 0; j < c; j++){
        float2 e = g_end[(b*NCH_ + j)*N_ + n];
        float tr = cr*lLr - ci*lLi + e.x;
        float ti = cr*lLi + ci*lLr + e.y;
        cr = tr; ci = ti;
    }

    __half2* p = g_xh + ((size_t)(b*T_ + c*L_))*N_ + n;
    float xr = cr, xi = ci;
    for (int t0 = 0; t0 < L_; t0 += 16){
        __half2 v[16];
        #pragma unroll
        for (int j = 0; j < 16; j++) v[j] = p[(size_t)(t0+j)*N_];
        #pragma unroll
        for (int j = 0; j < 16; j++){
            float2 q = __half22float2(v[j]);
            float nr = fmaf(lr, xr, fmaf(-li, xi, q.x));
            float ni = fmaf(lr, xi, fmaf( li, xr, q.y));
            xr = nr; xi = ni;
            p[(size_t)(t0+j)*N_] = __floats2half2_rn(xr, xi);
        }
    }
}

// ---------------------------------------------------------------------------
extern "C" void kernel_launch(void* const* d_in, const int* in_sizes, int n_in,
                              void* d_out, int out_size)
{
    const float* u     = (const float*)d_in[0];
    const float* C_re  = (const float*)d_in[1];
    const float* C_im  = (const float*)d_in[2];
    const float* B_re  = (const float*)d_in[3];
    const float* B_im  = (const float*)d_in[4];
    const float* D     = (const float*)d_in[5];
    const float* nu    = (const float*)d_in[6];
    const float* theta = (const float*)d_in[7];
    const float* gamma = (const float*)d_in[8];
    float* y = (float*)d_out;

    const int SMEM1 = 2*(16384 + 64*128);   // 49152
    const int SMEM2 = 2*(16384 + 32*128);   // 40960
    cudaFuncSetAttribute(gemm_tc<1>, cudaFuncAttributeMaxDynamicSharedMemorySize, SMEM1);
    cudaFuncSetAttribute(gemm_tc<2>, cudaFuncAttributeMaxDynamicSharedMemorySize, SMEM2);

    prep_W<<<256, 256>>>(B_re, B_im, C_re, C_im, gamma);

    gemm_tc<1><<<dim3(16, M_/128), 256, SMEM1>>>(u, D, u, (float*)0);

    scan_ends<<<512, 256>>>(nu, theta);
    scan_apply<<<512, 256>>>(nu, theta);

    gemm_tc<2><<<dim3(16, M_/128), 256, SMEM2>>>((const float*)0, D, u, y);
}

// round 9
// speedup vs baseline: 2.0151x; 2.0151x over previous
#include <cuda_runtime.h>
#include <cuda_fp16.h>
#include <cstdint>

#define B_   8
#define T_   2048
#define N_   512
#define M_   (B_*T_)      // 16384
#define L_   32           // scan chunk length
#define NCH_ (T_/L_)      // 64

#define WSCALE 64.0f
#define WINV   (1.0f/64.0f)

typedef unsigned long long ull;

// Scratch
__device__ __half  g_uh[M_*N_];               // u as fp16
__device__ __half2 g_xh[M_*N_];               // x as fp16 complex (re=low, im=high)
__device__ float2  g_end[B_*NCH_*N_];
// Pre-transposed/swizzled fp16 weight tiles (scaled by WSCALE):
__device__ uint4 g_W1[8][8][1024];            // GEMM1 B'' (Neff=1024, K=512), 128-row blocks
__device__ uint4 g_W2[4][16][1024];           // GEMM2 B'  (N=512, Keff=1024), 128-row blocks

// ---------------------------------------------------------------------------
// Helpers
// ---------------------------------------------------------------------------
__device__ __forceinline__ uint32_t s2u(const void* p){
    uint32_t a;
    asm("{ .reg .u64 t; cvta.to.shared.u64 t, %1; cvt.u32.u64 %0, t; }" : "=r"(a) : "l"(p));
    return a;
}
#define SWZ(o) ((uint32_t)(o) ^ ((((uint32_t)(o))>>3)&0x70u))

__device__ __forceinline__ uint32_t cvt2h(float x0, float x1){
    uint32_t r;
    asm("cvt.rn.f16x2.f32 %0, %1, %2;" : "=r"(r) : "f"(x1), "f"(x0));
    return r;
}
__device__ __forceinline__ uint4 ldsm4(uint32_t addr){
    uint4 r;
    asm volatile("ldmatrix.sync.aligned.m8n8.x4.shared.b16 {%0,%1,%2,%3}, [%4];"
        : "=r"(r.x), "=r"(r.y), "=r"(r.z), "=r"(r.w) : "r"(addr));
    return r;
}
__device__ __forceinline__ void mma16816(float* c, uint4 a, uint32_t b0, uint32_t b1){
    asm volatile("mma.sync.aligned.m16n8k16.row.col.f32.f16.f16.f32 "
        "{%0,%1,%2,%3}, {%4,%5,%6,%7}, {%8,%9}, {%0,%1,%2,%3};"
        : "+f"(c[0]), "+f"(c[1]), "+f"(c[2]), "+f"(c[3])
        : "r"(a.x), "r"(a.y), "r"(a.z), "r"(a.w), "r"(b0), "r"(b1));
}
__device__ __forceinline__ void cpasync16(uint32_t dst, const void* src){
    asm volatile("cp.async.cg.shared.global [%0], [%1], 16;" :: "r"(dst), "l"(src));
}

// ---------------------------------------------------------------------------
// u -> fp16 (once)
// ---------------------------------------------------------------------------
__global__ __launch_bounds__(256) void cvt_u(const float* __restrict__ u){
    int i = blockIdx.x * 256 + threadIdx.x;      // 2M units of 8 elements
    const float4* p = (const float4*)(u) + i*2;
    float4 a = p[0], b = p[1];
    uint4 H;
    H.x = cvt2h(a.x, a.y);
    H.y = cvt2h(a.z, a.w);
    H.z = cvt2h(b.x, b.y);
    H.w = cvt2h(b.z, b.w);
    ((uint4*)g_uh)[i] = H;
}

// ---------------------------------------------------------------------------
// Prepass (smem-transposed, coalesced loads).
// ---------------------------------------------------------------------------
__global__ __launch_bounds__(256) void prep_W(const float* __restrict__ Bre,
                                              const float* __restrict__ Bim,
                                              const float* __restrict__ Cre,
                                              const float* __restrict__ Cim,
                                              const float* __restrict__ gamma)
{
    __shared__ float s0[64*36];
    __shared__ float s1[64*36];
    __shared__ float gs[64];
    int bid = blockIdx.x, tid = threadIdx.x;

    if (bid < 128){
        int kb = bid >> 4, nt = bid & 15;
        int n0 = nt*32, k0 = kb*64;
        #pragma unroll
        for (int i = 0; i < 2; i++){
            int idx = tid + 256*i;
            int row = idx >> 3, c4 = (idx & 7) * 4;
            *(float4*)&s0[row*36 + c4] = *(const float4*)&Bre[(size_t)(k0+row)*N_ + n0 + c4];
            *(float4*)&s1[row*36 + c4] = *(const float4*)&Bim[(size_t)(k0+row)*N_ + n0 + c4];
        }
        if (tid < 64) gs[tid] = gamma[k0 + tid];
        __syncthreads();
        #pragma unroll
        for (int i = 0; i < 2; i++){
            int uid = tid + 256*i;
            int jloc = uid >> 3, cl = uid & 7;
            int j = n0*2 + jloc;
            int nloc = jloc >> 1, p = jloc & 1;
            const float* sp = p ? s1 : s0;
            float vs[8];
            #pragma unroll
            for (int e = 0; e < 8; e++){
                int kl = cl*8 + e;
                vs[e] = sp[kl*36 + nloc] * gs[kl] * WSCALE;
            }
            uint4 H;
            H.x = cvt2h(vs[0], vs[1]);
            H.y = cvt2h(vs[2], vs[3]);
            H.z = cvt2h(vs[4], vs[5]);
            H.w = cvt2h(vs[6], vs[7]);
            int jl = j & 127;
            g_W1[j>>7][kb][jl*8 + (cl ^ (jl & 7))] = H;
        }
    } else {
        bid -= 128;
        int kb = bid >> 3, jt = bid & 7;
        int j0 = jt*64, k0 = kb*32;
        #pragma unroll
        for (int i = 0; i < 2; i++){
            int idx = tid + 256*i;
            int row = idx >> 4, c4 = (idx & 15) * 4;
            *(float4*)&s0[row*68 + c4] = *(const float4*)&Cre[(size_t)(k0+row)*N_ + j0 + c4];
            *(float4*)&s1[row*68 + c4] = *(const float4*)&Cim[(size_t)(k0+row)*N_ + j0 + c4];
        }
        __syncthreads();
        #pragma unroll
        for (int i = 0; i < 2; i++){
            int uid = tid + 256*i;
            int jloc = uid >> 3, cl = uid & 7;
            int j = j0 + jloc;
            float vs[8];
            #pragma unroll
            for (int e = 0; e < 8; e++){
                int kel = cl*8 + e;
                int kl = kel >> 1;
                float v = (kel & 1) ? -s1[kl*68 + jloc] : s0[kl*68 + jloc];
                vs[e] = v * WSCALE;
            }
            uint4 H;
            H.x = cvt2h(vs[0], vs[1]);
            H.y = cvt2h(vs[2], vs[3]);
            H.z = cvt2h(vs[4], vs[5]);
            H.w = cvt2h(vs[6], vs[7]);
            int jl = j & 127;
            g_W2[j>>7][kb][jl*8 + (cl ^ (jl & 7))] = H;
        }
    }
}

// ---------------------------------------------------------------------------
// HMMA GEMM, fp16, pure cp.async A+B, double-buffered, 128x128 tile, 8 warps
// (4x2), warp tile 32x64.
// MODE 1: g_xh = uh @ W1,  A=g_uh (rowB=1024B), KIT=8,  nb grid 8
// MODE 2: y = flat(g_xh) @ W2 + D*u, A=g_xh (rowB=2048B), KIT=16, nb grid 4
// ---------------------------------------------------------------------------
template<int MODE>
__global__ __launch_bounds__(256, 2) void gemm_tc(const float* __restrict__ Dv,
                                                  float* __restrict__ yout)
{
    constexpr int KIT = (MODE == 1) ? 8 : 16;
    constexpr int ROWB = (MODE == 1) ? 1024 : 2048;   // A row stride in bytes
    constexpr uint32_t STG = 32768;
    constexpr uint32_t AH = 0, BH = 16384;

    extern __shared__ char sm[];
    const uint32_t sb = s2u(sm);

    const int tid  = threadIdx.x;
    const int lane = tid & 31, warp = tid >> 5;
    const int wm = warp >> 1, wn = warp & 1;
    const int nb = blockIdx.x;              // n-block FAST -> A stripe reuse in L2
    const int m0 = blockIdx.y * 128;

    const char* Abase = (MODE == 1) ? (const char*)g_uh : (const char*)g_xh;
    const uint4* Wb = (MODE == 1) ? &g_W1[nb][0][0] : &g_W2[nb][0][0];

    float acc[2][8][4];
    #pragma unroll
    for (int a = 0; a < 2; a++)
        #pragma unroll
        for (int b = 0; b < 8; b++)
            #pragma unroll
            for (int q = 0; q < 4; q++) acc[a][b][q] = 0.f;

    // A cp.async mapping: 1024 16B units: row = idx>>3, un = idx&7
    // ---- prologue: stage 0 ----
    {
        #pragma unroll
        for (int i = 0; i < 4; i++)
            cpasync16(sb + BH + (tid + 256*i)*16, Wb + tid + 256*i);
        #pragma unroll
        for (int i = 0; i < 4; i++){
            int idx = tid + 256*i, row = idx >> 3, un = idx & 7;
            cpasync16(sb + AH + SWZ(row*128 + un*16),
                      Abase + (size_t)(m0+row)*ROWB + un*16);
        }
        asm volatile("cp.async.commit_group;");
    }

    for (int kb = 0; kb < KIT; kb++){
        const uint32_t sc = sb + (kb & 1)*STG;
        const uint32_t sn = sb + ((kb & 1) ^ 1)*STG;

        if (kb + 1 < KIT){
            const uint4* wh = Wb + (kb+1)*1024;
            #pragma unroll
            for (int i = 0; i < 4; i++)
                cpasync16(sn + BH + (tid + 256*i)*16, wh + tid + 256*i);
            #pragma unroll
            for (int i = 0; i < 4; i++){
                int idx = tid + 256*i, row = idx >> 3, un = idx & 7;
                cpasync16(sn + AH + SWZ(row*128 + un*16),
                          Abase + (size_t)(m0+row)*ROWB + (kb+1)*128 + un*16);
            }
            asm volatile("cp.async.commit_group;");
            asm volatile("cp.async.wait_group 1;" ::: "memory");
        } else {
            asm volatile("cp.async.wait_group 0;" ::: "memory");
        }
        __syncthreads();

        #pragma unroll
        for (int kk = 0; kk < 4; kk++){
            uint4 ah[2];
            #pragma unroll
            for (int mt = 0; mt < 2; mt++){
                uint32_t off = SWZ((wm*32 + mt*16 + (lane&15))*128 + (kk*2 + (lane>>4))*16);
                ah[mt] = ldsm4(sc + AH + off);
            }
            #pragma unroll
            for (int bt = 0; bt < 4; bt++){
                uint32_t off = SWZ((wn*64 + bt*16 + (lane&7) + ((lane>>4)<<3))*128
                                   + (kk*2 + ((lane>>3)&1))*16);
                uint4 bh = ldsm4(sc + BH + off);
                #pragma unroll
                for (int mt = 0; mt < 2; mt++){
                    mma16816(acc[mt][2*bt],   ah[mt], bh.x, bh.y);
                    mma16816(acc[mt][2*bt+1], ah[mt], bh.z, bh.w);
                }
            }
        }
        __syncthreads();
    }

    // Epilogue (undo WSCALE)
    const int mrow = lane >> 2;
    const int ncol = (lane & 3) * 2;
    if (MODE == 1){
        #pragma unroll
        for (int mt = 0; mt < 2; mt++){
            #pragma unroll
            for (int nf = 0; nf < 8; nf++){
                int m    = m0 + wm*32 + mt*16 + mrow;
                int neff = nb*128 + wn*64 + nf*8 + ncol;
                int nc   = neff >> 1;
                g_xh[(size_t)m*N_ + nc]     = __floats2half2_rn(acc[mt][nf][0]*WINV, acc[mt][nf][1]*WINV);
                g_xh[(size_t)(m+8)*N_ + nc] = __floats2half2_rn(acc[mt][nf][2]*WINV, acc[mt][nf][3]*WINV);
            }
        }
    } else {
        #pragma unroll
        for (int mt = 0; mt < 2; mt++){
            #pragma unroll
            for (int nf = 0; nf < 8; nf++){
                int m = m0 + wm*32 + mt*16 + mrow;
                int n = nb*128 + wn*64 + nf*8 + ncol;
                float2 d = *(const float2*)&Dv[n];
                size_t i0 = (size_t)m*N_ + n;
                size_t i1 = (size_t)(m+8)*N_ + n;
                float2 u0 = __half22float2(*(const __half2*)&g_uh[i0]);
                float2 u1 = __half22float2(*(const __half2*)&g_uh[i1]);
                float2 y0 = make_float2(fmaf(d.x, u0.x, acc[mt][nf][0]*WINV),
                                        fmaf(d.y, u0.y, acc[mt][nf][1]*WINV));
                float2 y1 = make_float2(fmaf(d.x, u1.x, acc[mt][nf][2]*WINV),
                                        fmaf(d.y, u1.y, acc[mt][nf][3]*WINV));
                *(float2*)&yout[i0] = y0;
                *(float2*)&yout[i1] = y1;
            }
        }
    }
}

// ---------------------------------------------------------------------------
// Scan pass 1: chunk end-states only (read-only)
// ---------------------------------------------------------------------------
__global__ __launch_bounds__(256) void scan_ends(const float* __restrict__ nu,
                                                 const float* __restrict__ theta)
{
    int gid = blockIdx.x * 256 + threadIdx.x;   // 262144 threads
    int n = gid & (N_-1);
    int c = (gid >> 9) & (NCH_-1);
    int b = gid >> 15;

    float en  = expf(nu[n]);
    float mag = expf(-en);
    float th  = theta[n];
    float lr  = mag * cosf(th);
    float li  = mag * sinf(th);

    const __half2* p = g_xh + ((size_t)(b*T_ + c*L_))*N_ + n;
    float er = 0.f, ei = 0.f;
    for (int t0 = 0; t0 < L_; t0 += 16){
        __half2 v[16];
        #pragma unroll
        for (int j = 0; j < 16; j++) v[j] = p[(size_t)(t0+j)*N_];
        #pragma unroll
        for (int j = 0; j < 16; j++){
            float2 q = __half22float2(v[j]);
            float nr = fmaf(lr, er, fmaf(-li, ei, q.x));
            float ni = fmaf(lr, ei, fmaf( li, er, q.y));
            er = nr; ei = ni;
        }
    }
    g_end[(b*NCH_ + c)*N_ + n] = make_float2(er, ei);
}

// ---------------------------------------------------------------------------
// Scan pass 2: carry (Horner over chunk ends) + full recurrence, write x.
// ---------------------------------------------------------------------------
__global__ __launch_bounds__(256) void scan_apply(const float* __restrict__ nu,
                                                  const float* __restrict__ theta)
{
    int gid = blockIdx.x * 256 + threadIdx.x;
    int n = gid & (N_-1);
    int c = (gid >> 9) & (NCH_-1);
    int b = gid >> 15;

    float en  = expf(nu[n]);
    float mag = expf(-en);
    float th  = theta[n];
    float lr  = mag * cosf(th);
    float li  = mag * sinf(th);

    float magL = expf(-(float)L_ * en);
    float aL   = (float)L_ * th;
    float lLr  = magL * cosf(aL);
    float lLi  = magL * sinf(aL);

    float cr = 0.f, ci = 0.f;
    for (int j = 0; j < c; j++){
        float2 e = g_end[(b*NCH_ + j)*N_ + n];
        float tr = cr*lLr - ci*lLi + e.x;
        float ti = cr*lLi + ci*lLr + e.y;
        cr = tr; ci = ti;
    }

    __half2* p = g_xh + ((size_t)(b*T_ + c*L_))*N_ + n;
    float xr = cr, xi = ci;
    for (int t0 = 0; t0 < L_; t0 += 16){
        __half2 v[16];
        #pragma unroll
        for (int j = 0; j < 16; j++) v[j] = p[(size_t)(t0+j)*N_];
        #pragma unroll
        for (int j = 0; j < 16; j++){
            float2 q = __half22float2(v[j]);
            float nr = fmaf(lr, xr, fmaf(-li, xi, q.x));
            float ni = fmaf(lr, xi, fmaf( li, xr, q.y));
            xr = nr; xi = ni;
            p[(size_t)(t0+j)*N_] = __floats2half2_rn(xr, xi);
        }
    }
}

// ---------------------------------------------------------------------------
extern "C" void kernel_launch(void* const* d_in, const int* in_sizes, int n_in,
                              void* d_out, int out_size)
{
    const float* u     = (const float*)d_in[0];
    const float* C_re  = (const float*)d_in[1];
    const float* C_im  = (const float*)d_in[2];
    const float* B_re  = (const float*)d_in[3];
    const float* B_im  = (const float*)d_in[4];
    const float* D     = (const float*)d_in[5];
    const float* nu    = (const float*)d_in[6];
    const float* theta = (const float*)d_in[7];
    const float* gamma = (const float*)d_in[8];
    float* y = (float*)d_out;

    const int SMEM = 65536;
    cudaFuncSetAttribute(gemm_tc<1>, cudaFuncAttributeMaxDynamicSharedMemorySize, SMEM);
    cudaFuncSetAttribute(gemm_tc<2>, cudaFuncAttributeMaxDynamicSharedMemorySize, SMEM);

    cvt_u<<<M_*N_/8/256, 256>>>(u);
    prep_W<<<256, 256>>>(B_re, B_im, C_re, C_im, gamma);

    gemm_tc<1><<<dim3(8, M_/128), 256, SMEM>>>(D, (float*)0);

    scan_ends<<<1024, 256>>>(nu, theta);
    scan_apply<<<1024, 256>>>(nu, theta);

    gemm_tc<2><<<dim3(4, M_/128), 256, SMEM>>>(D, y);
}